// round 1
// baseline (speedup 1.0000x reference)
#include <cuda_runtime.h>

// Problem constants (fixed shapes from the reference)
#define E_DIM   1024
#define M_TOT   4096     // 2 * 2048 rows of x
#define SEQ     2048
#define NBATCH  32       // b * h
#define HD      64       // head dim

// Scratch for Q/K/V projections (48 MB total). __device__ globals are the
// sanctioned scratch mechanism (no cudaMalloc allowed).
__device__ float g_Q[M_TOT * E_DIM];
__device__ float g_K[M_TOT * E_DIM];
__device__ float g_V[M_TOT * E_DIM];

// ---------------------------------------------------------------------------
// Projection GEMM: C[M,N] = X[M,K] @ W[N,K]^T + bias[N]
// blockIdx.z selects which of Wq/Wk/Wv. 128x128 tile, BK=16, 256 threads,
// 8x8 register blocking with strided column mapping (conflict-free LDS).
// ---------------------------------------------------------------------------
__global__ __launch_bounds__(256) void proj_kernel(
    const float* __restrict__ X,
    const float* __restrict__ Wq, const float* __restrict__ bq,
    const float* __restrict__ Wk, const float* __restrict__ bk,
    const float* __restrict__ Wv, const float* __restrict__ bv)
{
    const float* W;
    const float* bias;
    float* C;
    if (blockIdx.z == 0)      { W = Wq; bias = bq; C = g_Q; }
    else if (blockIdx.z == 1) { W = Wk; bias = bk; C = g_K; }
    else                      { W = Wv; bias = bv; C = g_V; }

    const int BM = 128, BN = 128, BK = 16;
    __shared__ float Xs[BK][BM + 1];   // [k][m], pad 1 -> stride 129 (odd)
    __shared__ float Ws[BK][BN + 1];   // [k][n]

    const int tid = threadIdx.x;
    const int tx  = tid & 15;          // n direction (strided)
    const int ty  = tid >> 4;          // m direction (strided)
    const int m0  = blockIdx.y * BM;
    const int n0  = blockIdx.x * BN;

    float acc[8][8];
#pragma unroll
    for (int i = 0; i < 8; i++)
#pragma unroll
        for (int j = 0; j < 8; j++) acc[i][j] = 0.f;

    for (int k0 = 0; k0 < E_DIM; k0 += BK) {
        // Load X tile [128 rows][16 k] and W tile [128 rows][16 k], each
        // 512 float4 -> 2 float4 per thread per matrix. Store transposed.
#pragma unroll
        for (int r = 0; r < 2; r++) {
            int idx = tid + r * 256;           // 0..511
            int row = idx >> 2;                // 0..127
            int kq  = (idx & 3) * 4;           // 0,4,8,12
            float4 v = *(const float4*)&X[(size_t)(m0 + row) * E_DIM + k0 + kq];
            Xs[kq + 0][row] = v.x; Xs[kq + 1][row] = v.y;
            Xs[kq + 2][row] = v.z; Xs[kq + 3][row] = v.w;
            float4 w = *(const float4*)&W[(size_t)(n0 + row) * E_DIM + k0 + kq];
            Ws[kq + 0][row] = w.x; Ws[kq + 1][row] = w.y;
            Ws[kq + 2][row] = w.z; Ws[kq + 3][row] = w.w;
        }
        __syncthreads();

#pragma unroll
        for (int kk = 0; kk < BK; kk++) {
            float a[8], b[8];
#pragma unroll
            for (int i = 0; i < 8; i++) a[i] = Xs[kk][ty + 16 * i];
#pragma unroll
            for (int j = 0; j < 8; j++) b[j] = Ws[kk][tx + 16 * j];
#pragma unroll
            for (int i = 0; i < 8; i++)
#pragma unroll
                for (int j = 0; j < 8; j++)
                    acc[i][j] = fmaf(a[i], b[j], acc[i][j]);
        }
        __syncthreads();
    }

#pragma unroll
    for (int i = 0; i < 8; i++) {
        int m = m0 + ty + 16 * i;
#pragma unroll
        for (int j = 0; j < 8; j++) {
            int n = n0 + tx + 16 * j;
            C[(size_t)m * E_DIM + n] = acc[i][j] + bias[n];
        }
    }
}

// ---------------------------------------------------------------------------
// Attention (no softmax, per the reference!): for each of 32 "batches"
//   O = (Q K^T * 0.125) @ V    with Q,K,V,O = [2048, 64]
// CTA = (batch, 128-row q tile). Stream K/V in 64-row chunks through smem.
// Phase A: S[128][64] = Q_tile @ Kchunk^T  (regs -> smem, scaled)
// Phase B: O[128][64] += S @ Vchunk        (accumulated in regs)
// Strided column mapping c = tx + 16*j keeps the hot LDS paths conflict-free.
// ---------------------------------------------------------------------------
#define PADR 65   // row stride (odd) for all smem tiles

__global__ __launch_bounds__(256) void attn_kernel(float* __restrict__ out)
{
    const int b  = blockIdx.y;            // 0..31
    const int q0 = blockIdx.x * 128;      // q tile start
    const float* Q = g_Q + (size_t)b * SEQ * HD;
    const float* K = g_K + (size_t)b * SEQ * HD;
    const float* V = g_V + (size_t)b * SEQ * HD;
    float* O = out + (size_t)b * SEQ * HD;

    extern __shared__ float sm[];
    float* Qs = sm;                        // [128][PADR]
    float* Ks = Qs + 128 * PADR;           // [64][PADR]
    float* Vs = Ks + 64 * PADR;            // [64][PADR]
    float* Ss = Vs + 64 * PADR;            // [128][PADR]

    const int tid = threadIdx.x;
    const int tx  = tid & 15;
    const int ty  = tid >> 4;
    const float scale = 0.125f;            // 1/sqrt(64)

    // Load Q tile: 128x64 floats = 2048 float4 -> 8 per thread.
#pragma unroll
    for (int r = 0; r < 8; r++) {
        int idx = tid + r * 256;           // 0..2047
        int row = idx >> 4;                // 0..127
        int c   = (idx & 15) * 4;
        float4 v = *(const float4*)&Q[(size_t)(q0 + row) * HD + c];
        float* dst = &Qs[row * PADR + c];
        dst[0] = v.x; dst[1] = v.y; dst[2] = v.z; dst[3] = v.w;
    }

    float accO[8][4];
#pragma unroll
    for (int i = 0; i < 8; i++)
#pragma unroll
        for (int j = 0; j < 4; j++) accO[i][j] = 0.f;

    for (int k0 = 0; k0 < SEQ; k0 += 64) {
        __syncthreads();   // prev Phase B done before overwriting Ks/Vs;
                           // also orders the initial Qs fill before Phase A.
        // Load K,V chunks: each 64x64 = 1024 float4 -> 4 per thread each.
#pragma unroll
        for (int r = 0; r < 4; r++) {
            int idx = tid + r * 256;       // 0..1023
            int row = idx >> 4;            // 0..63
            int c   = (idx & 15) * 4;
            float4 kv = *(const float4*)&K[(size_t)(k0 + row) * HD + c];
            float* dk = &Ks[row * PADR + c];
            dk[0] = kv.x; dk[1] = kv.y; dk[2] = kv.z; dk[3] = kv.w;
            float4 vv = *(const float4*)&V[(size_t)(k0 + row) * HD + c];
            float* dv = &Vs[row * PADR + c];
            dv[0] = vv.x; dv[1] = vv.y; dv[2] = vv.z; dv[3] = vv.w;
        }
        __syncthreads();

        // Phase A: S[r][c] = sum_d Q[r][d] * K[c][d]
        float s_[8][4];
#pragma unroll
        for (int i = 0; i < 8; i++)
#pragma unroll
            for (int j = 0; j < 4; j++) s_[i][j] = 0.f;

#pragma unroll 8
        for (int d = 0; d < HD; d++) {
            float qr[8], kc[4];
#pragma unroll
            for (int i = 0; i < 8; i++) qr[i] = Qs[(ty * 8 + i) * PADR + d];
#pragma unroll
            for (int j = 0; j < 4; j++) kc[j] = Ks[(tx + 16 * j) * PADR + d];
#pragma unroll
            for (int i = 0; i < 8; i++)
#pragma unroll
                for (int j = 0; j < 4; j++)
                    s_[i][j] = fmaf(qr[i], kc[j], s_[i][j]);
        }

        // Scale + stage S in smem for Phase B's row-wise reads.
#pragma unroll
        for (int i = 0; i < 8; i++)
#pragma unroll
            for (int j = 0; j < 4; j++)
                Ss[(ty * 8 + i) * PADR + tx + 16 * j] = s_[i][j] * scale;
        __syncthreads();

        // Phase B: O[r][c] += sum_kk S[r][kk] * V[kk][c]
#pragma unroll 8
        for (int kk = 0; kk < 64; kk++) {
            float sv[8], vv[4];
#pragma unroll
            for (int i = 0; i < 8; i++) sv[i] = Ss[(ty * 8 + i) * PADR + kk];
#pragma unroll
            for (int j = 0; j < 4; j++) vv[j] = Vs[kk * PADR + tx + 16 * j];
#pragma unroll
            for (int i = 0; i < 8; i++)
#pragma unroll
                for (int j = 0; j < 4; j++)
                    accO[i][j] = fmaf(sv[i], vv[j], accO[i][j]);
        }
    }

    // Write O tile (coalesced across tx).
#pragma unroll
    for (int i = 0; i < 8; i++) {
        int r = q0 + ty * 8 + i;
#pragma unroll
        for (int j = 0; j < 4; j++)
            O[(size_t)r * HD + tx + 16 * j] = accO[i][j];
    }
}

// ---------------------------------------------------------------------------
extern "C" void kernel_launch(void* const* d_in, const int* in_sizes, int n_in,
                              void* d_out, int out_size)
{
    const float* x  = (const float*)d_in[0];
    const float* Wq = (const float*)d_in[1];
    const float* bq = (const float*)d_in[2];
    const float* Wk = (const float*)d_in[3];
    const float* bk = (const float*)d_in[4];
    const float* Wv = (const float*)d_in[5];
    const float* bv = (const float*)d_in[6];
    float* out = (float*)d_out;

    // 97.5 KB dynamic smem for the attention kernel (idempotent; not an
    // allocation, legal under graph capture).
    const int attn_smem = (128 + 64 + 64 + 128) * PADR * (int)sizeof(float);
    cudaFuncSetAttribute(attn_kernel,
                         cudaFuncAttributeMaxDynamicSharedMemorySize,
                         attn_smem);

    // 1) Q/K/V projections: grid (N/128, M/128, 3)
    dim3 pgrid(E_DIM / 128, M_TOT / 128, 3);
    proj_kernel<<<pgrid, 256>>>(x, Wq, bq, Wk, bk, Wv, bv);

    // 2) Attention: grid (q-tiles, batches)
    dim3 agrid(SEQ / 128, NBATCH);
    attn_kernel<<<agrid, 256, attn_smem>>>(out);
}

// round 2
// speedup vs baseline: 3.2808x; 3.2808x over previous
#include <cuda_runtime.h>

// Problem constants (fixed shapes from the reference)
#define E_DIM   1024
#define M_TOT   4096     // 2 * 2048 rows of x
#define SEQ     2048
#define NBATCH  32       // b * h
#define HD      64       // head dim

// Scratch for Q/K/V projections (48 MB total).
__device__ float g_Q[M_TOT * E_DIM];
__device__ float g_K[M_TOT * E_DIM];
__device__ float g_V[M_TOT * E_DIM];

// ---------------------------------------------------------------------------
// Helpers: tf32 rounding + m16n8k8 tf32 tensor-core MMA
// ---------------------------------------------------------------------------
__device__ __forceinline__ float f2tf32(float x) {
    unsigned u;
    asm("cvt.rna.tf32.f32 %0, %1;" : "=r"(u) : "f"(x));
    return __uint_as_float(u);
}

__device__ __forceinline__ void mma_tf32(float c[4], const unsigned a[4],
                                         const unsigned b[2]) {
    asm volatile(
        "mma.sync.aligned.m16n8k8.row.col.f32.tf32.tf32.f32 "
        "{%0,%1,%2,%3}, {%4,%5,%6,%7}, {%8,%9}, {%0,%1,%2,%3};"
        : "+f"(c[0]), "+f"(c[1]), "+f"(c[2]), "+f"(c[3])
        : "r"(a[0]), "r"(a[1]), "r"(a[2]), "r"(a[3]), "r"(b[0]), "r"(b[1]));
}

// ---------------------------------------------------------------------------
// Projection GEMM (tensor cores): C[M,N] = X[M,K] @ W[N,K]^T + bias[N]
// CTA tile 128x128, BK=32, 8 warps (2 x 4), warp tile 64x32.
// Smem tiles stored row-major [row][k] with stride 36 (36%32==4 ->
// fragment loads hit banks 4*(lane/4)+lane%4, all distinct).
// ---------------------------------------------------------------------------
#define P_LD 36

__global__ __launch_bounds__(256) void proj_kernel(
    const float* __restrict__ X,
    const float* __restrict__ Wq, const float* __restrict__ bq,
    const float* __restrict__ Wk, const float* __restrict__ bk,
    const float* __restrict__ Wv, const float* __restrict__ bv)
{
    const float* W;
    const float* bias;
    float* C;
    if (blockIdx.z == 0)      { W = Wq; bias = bq; C = g_Q; }
    else if (blockIdx.z == 1) { W = Wk; bias = bk; C = g_K; }
    else                      { W = Wv; bias = bv; C = g_V; }

    __shared__ float Xs[128 * P_LD];   // [m][k], tf32 values
    __shared__ float Ws[128 * P_LD];   // [n][k], tf32 values

    const int tid   = threadIdx.x;
    const int lane  = tid & 31;
    const int warp  = tid >> 5;
    const int warpM = warp >> 2;        // 0..1
    const int warpN = warp & 3;         // 0..3
    const int g     = lane >> 2;        // 0..7
    const int tg    = lane & 3;         // 0..3
    const int m0    = blockIdx.y * 128;
    const int n0    = blockIdx.x * 128;

    float acc[4][4][4];                 // [mi][nj][frag]
#pragma unroll
    for (int i = 0; i < 4; i++)
#pragma unroll
        for (int j = 0; j < 4; j++)
#pragma unroll
            for (int f = 0; f < 4; f++) acc[i][j][f] = 0.f;

    for (int k0 = 0; k0 < E_DIM; k0 += 32) {
        // Fill tiles: 128x32 floats each = 1024 float4 -> 4 per thread each.
#pragma unroll
        for (int r = 0; r < 4; r++) {
            int idx = tid + r * 256;        // 0..1023
            int row = idx >> 3;             // 0..127
            int c4  = (idx & 7) * 4;        // 0,4,...,28
            float4 v = *(const float4*)&X[(size_t)(m0 + row) * E_DIM + k0 + c4];
            float* dx = &Xs[row * P_LD + c4];
            dx[0] = f2tf32(v.x); dx[1] = f2tf32(v.y);
            dx[2] = f2tf32(v.z); dx[3] = f2tf32(v.w);
            float4 w = *(const float4*)&W[(size_t)(n0 + row) * E_DIM + k0 + c4];
            float* dw = &Ws[row * P_LD + c4];
            dw[0] = f2tf32(w.x); dw[1] = f2tf32(w.y);
            dw[2] = f2tf32(w.z); dw[3] = f2tf32(w.w);
        }
        __syncthreads();

#pragma unroll
        for (int kk = 0; kk < 4; kk++) {    // 4 k-steps of 8
            const int kb = kk * 8;
            unsigned a[4][4], b[4][2];
#pragma unroll
            for (int i = 0; i < 4; i++) {
                int row = warpM * 64 + i * 16;
                a[i][0] = __float_as_uint(Xs[(row + g)     * P_LD + kb + tg]);
                a[i][1] = __float_as_uint(Xs[(row + g + 8) * P_LD + kb + tg]);
                a[i][2] = __float_as_uint(Xs[(row + g)     * P_LD + kb + tg + 4]);
                a[i][3] = __float_as_uint(Xs[(row + g + 8) * P_LD + kb + tg + 4]);
            }
#pragma unroll
            for (int j = 0; j < 4; j++) {
                int n = warpN * 32 + j * 8;
                b[j][0] = __float_as_uint(Ws[(n + g) * P_LD + kb + tg]);
                b[j][1] = __float_as_uint(Ws[(n + g) * P_LD + kb + tg + 4]);
            }
#pragma unroll
            for (int i = 0; i < 4; i++)
#pragma unroll
                for (int j = 0; j < 4; j++)
                    mma_tf32(acc[i][j], a[i], b[j]);
        }
        __syncthreads();
    }

    // Epilogue: C-fragment layout c0:(g, tg*2) c1:+1 c2:(g+8, tg*2) c3:+1
#pragma unroll
    for (int i = 0; i < 4; i++) {
        int rbase = m0 + warpM * 64 + i * 16;
#pragma unroll
        for (int j = 0; j < 4; j++) {
            int col = n0 + warpN * 32 + j * 8 + tg * 2;
            float b0 = bias[col], b1 = bias[col + 1];
            float2* p0 = (float2*)&C[(size_t)(rbase + g) * E_DIM + col];
            *p0 = make_float2(acc[i][j][0] + b0, acc[i][j][1] + b1);
            float2* p1 = (float2*)&C[(size_t)(rbase + g + 8) * E_DIM + col];
            *p1 = make_float2(acc[i][j][2] + b0, acc[i][j][3] + b1);
        }
    }
}

// ---------------------------------------------------------------------------
// Attention (no softmax): O = (Q K^T * 0.125) @ V per batch, tensor cores.
// CTA = 128 q-rows of one batch; 8 warps each own 16 q-rows.
// Loop over kk chunks of 64:
//   Phase A: S[16][64] = Q_rows @ Kchunk^T   (mma, staged to smem per-warp)
//   Phase B: O[16][64] += S @ Vchunk         (mma, accumulators persistent)
// Smem strides: Qs/Ks/Ss = 68 (A/B frag loads conflict-free: 68%32==4),
//               Vs = 72 (k-major B frag loads conflict-free: 72%32==8).
// ---------------------------------------------------------------------------
#define A_LDQ 68
#define A_LDV 72

__global__ __launch_bounds__(256) void attn_kernel(float* __restrict__ out)
{
    const int b  = blockIdx.y;
    const int q0 = blockIdx.x * 128;
    const float* Q = g_Q + (size_t)b * SEQ * HD;
    const float* K = g_K + (size_t)b * SEQ * HD;
    const float* V = g_V + (size_t)b * SEQ * HD;
    float* O = out + (size_t)b * SEQ * HD;

    extern __shared__ float sm[];
    float* Qs = sm;                          // [128][A_LDQ]
    float* Ks = Qs + 128 * A_LDQ;            // [64][A_LDQ]
    float* Vs = Ks + 64 * A_LDQ;             // [64][A_LDV]
    float* Ss = Vs + 64 * A_LDV;             // [128][A_LDQ]

    const int tid  = threadIdx.x;
    const int lane = tid & 31;
    const int warp = tid >> 5;               // 0..7 -> q rows [warp*16, +16)
    const int g    = lane >> 2;
    const int tg   = lane & 3;
    const int base = warp * 16;
    const float scale = 0.125f;

    // Load Q tile (tf32): 128x64 = 2048 float4 -> 8 per thread.
#pragma unroll
    for (int r = 0; r < 8; r++) {
        int idx = tid + r * 256;
        int row = idx >> 4;
        int c4  = (idx & 15) * 4;
        float4 v = *(const float4*)&Q[(size_t)(q0 + row) * HD + c4];
        float* d = &Qs[row * A_LDQ + c4];
        d[0] = f2tf32(v.x); d[1] = f2tf32(v.y);
        d[2] = f2tf32(v.z); d[3] = f2tf32(v.w);
    }

    float accO[8][4];
#pragma unroll
    for (int j = 0; j < 8; j++)
#pragma unroll
        for (int f = 0; f < 4; f++) accO[j][f] = 0.f;

    for (int k0 = 0; k0 < SEQ; k0 += 64) {
        __syncthreads();   // prev Phase B done with Vs; (iter0: orders Qs fill)
        // Load K,V chunks (tf32): each 64x64 = 1024 float4 -> 4 per thread.
#pragma unroll
        for (int r = 0; r < 4; r++) {
            int idx = tid + r * 256;
            int row = idx >> 4;
            int c4  = (idx & 15) * 4;
            float4 kv = *(const float4*)&K[(size_t)(k0 + row) * HD + c4];
            float* dk = &Ks[row * A_LDQ + c4];
            dk[0] = f2tf32(kv.x); dk[1] = f2tf32(kv.y);
            dk[2] = f2tf32(kv.z); dk[3] = f2tf32(kv.w);
            float4 vv = *(const float4*)&V[(size_t)(k0 + row) * HD + c4];
            float* dv = &Vs[row * A_LDV + c4];
            dv[0] = f2tf32(vv.x); dv[1] = f2tf32(vv.y);
            dv[2] = f2tf32(vv.z); dv[3] = f2tf32(vv.w);
        }
        __syncthreads();

        // ---- Phase A: S[16][64] = Q[16][64] @ K[64][64]^T
        float accS[8][4];
#pragma unroll
        for (int j = 0; j < 8; j++)
#pragma unroll
            for (int f = 0; f < 4; f++) accS[j][f] = 0.f;

#pragma unroll
        for (int ks = 0; ks < 8; ks++) {     // depth d = ks*8..+8
            const int kb = ks * 8;
            unsigned a[4];
            a[0] = __float_as_uint(Qs[(base + g)     * A_LDQ + kb + tg]);
            a[1] = __float_as_uint(Qs[(base + g + 8) * A_LDQ + kb + tg]);
            a[2] = __float_as_uint(Qs[(base + g)     * A_LDQ + kb + tg + 4]);
            a[3] = __float_as_uint(Qs[(base + g + 8) * A_LDQ + kb + tg + 4]);
#pragma unroll
            for (int j = 0; j < 8; j++) {    // kk-local tile
                unsigned bb[2];
                bb[0] = __float_as_uint(Ks[(j * 8 + g) * A_LDQ + kb + tg]);
                bb[1] = __float_as_uint(Ks[(j * 8 + g) * A_LDQ + kb + tg + 4]);
                mma_tf32(accS[j], a, bb);
            }
        }

        // Stage S (scaled, tf32) in this warp's own smem rows; warp-local.
#pragma unroll
        for (int j = 0; j < 8; j++) {
            int c = j * 8 + tg * 2;
            Ss[(base + g)     * A_LDQ + c]     = f2tf32(accS[j][0] * scale);
            Ss[(base + g)     * A_LDQ + c + 1] = f2tf32(accS[j][1] * scale);
            Ss[(base + g + 8) * A_LDQ + c]     = f2tf32(accS[j][2] * scale);
            Ss[(base + g + 8) * A_LDQ + c + 1] = f2tf32(accS[j][3] * scale);
        }
        __syncwarp();

        // ---- Phase B: O[16][64] += S[16][64] @ V[64][64]
#pragma unroll
        for (int ks = 0; ks < 8; ks++) {     // k = kk-local = ks*8..+8
            const int kb = ks * 8;
            unsigned a[4];
            a[0] = __float_as_uint(Ss[(base + g)     * A_LDQ + kb + tg]);
            a[1] = __float_as_uint(Ss[(base + g + 8) * A_LDQ + kb + tg]);
            a[2] = __float_as_uint(Ss[(base + g)     * A_LDQ + kb + tg + 4]);
            a[3] = __float_as_uint(Ss[(base + g + 8) * A_LDQ + kb + tg + 4]);
#pragma unroll
            for (int j = 0; j < 8; j++) {    // d tile
                unsigned bb[2];
                bb[0] = __float_as_uint(Vs[(kb + tg)     * A_LDV + j * 8 + g]);
                bb[1] = __float_as_uint(Vs[(kb + tg + 4) * A_LDV + j * 8 + g]);
                mma_tf32(accO[j], a, bb);
            }
        }
        __syncwarp();   // Phase B reads of Ss done before next chunk rewrites
    }

    // Epilogue: write O rows [q0+base, +16)
#pragma unroll
    for (int j = 0; j < 8; j++) {
        int c = j * 8 + tg * 2;
        float2* p0 = (float2*)&O[(size_t)(q0 + base + g) * HD + c];
        *p0 = make_float2(accO[j][0], accO[j][1]);
        float2* p1 = (float2*)&O[(size_t)(q0 + base + g + 8) * HD + c];
        *p1 = make_float2(accO[j][2], accO[j][3]);
    }
}

// ---------------------------------------------------------------------------
extern "C" void kernel_launch(void* const* d_in, const int* in_sizes, int n_in,
                              void* d_out, int out_size)
{
    const float* x  = (const float*)d_in[0];
    const float* Wq = (const float*)d_in[1];
    const float* bq = (const float*)d_in[2];
    const float* Wk = (const float*)d_in[3];
    const float* bk = (const float*)d_in[4];
    const float* Wv = (const float*)d_in[5];
    const float* bv = (const float*)d_in[6];
    float* out = (float*)d_out;

    const int attn_smem =
        (128 * A_LDQ + 64 * A_LDQ + 64 * A_LDV + 128 * A_LDQ) * (int)sizeof(float);
    cudaFuncSetAttribute(attn_kernel,
                         cudaFuncAttributeMaxDynamicSharedMemorySize,
                         attn_smem);

    dim3 pgrid(E_DIM / 128, M_TOT / 128, 3);
    proj_kernel<<<pgrid, 256>>>(x, Wq, bq, Wk, bk, Wv, bv);

    dim3 agrid(SEQ / 128, NBATCH);
    attn_kernel<<<agrid, 256, attn_smem>>>(out);
}